// round 1
// baseline (speedup 1.0000x reference)
#include <cuda_runtime.h>

// AttnDecoder single decode step.
// Live dataflow only (attention branch in the reference is dead code):
//   e = emb[tok]
//   gates = W_ih@e + b_ih + W_hh@h0 + b_hh ; LSTM cell -> h_new, c_new
//   logits = out_W @ h_new + out_b ; log_softmax
// Output layout (float32, out_size = V + 2H):
//   [0, V)        log_probs
//   [V, V+H)      h_new
//   [V+H, V+2H)   c_new

#define H 1024
#define V 50000

// Scratch (no allocations allowed in kernel_launch)
__device__ float g_h[H];
__device__ float g_logits[V];
__device__ float g_logZ;

// ---------------------------------------------------------------------------
// K1: fused gates matvec + LSTM cell.
// One warp per hidden element j: computes the 4 gate dots (rows j, H+j, 2H+j,
// 3H+j of W_ih and W_hh), then the elementwise cell update. e and h staged in
// shared memory once per block.
// grid = 256 blocks x 128 threads (4 warps) -> 1024 warps = 1024 elements.
// ---------------------------------------------------------------------------
__global__ void __launch_bounds__(128) k_lstm(
    const long long* __restrict__ tok_p,
    const float* __restrict__ emb,
    const float* __restrict__ h0,
    const float* __restrict__ c0,
    const float* __restrict__ W_ih,
    const float* __restrict__ W_hh,
    const float* __restrict__ b_ih,
    const float* __restrict__ b_hh,
    float* __restrict__ out)
{
    __shared__ float se[H];
    __shared__ float sh[H];

    const long long tok = *tok_p;
    const float* erow = emb + tok * (long long)H;
    for (int t = threadIdx.x; t < H; t += blockDim.x) {
        se[t] = erow[t];
        sh[t] = h0[t];
    }
    __syncthreads();

    const int warp = (blockIdx.x * blockDim.x + threadIdx.x) >> 5;
    const int lane = threadIdx.x & 31;
    const int j = warp;  // hidden element index, 0..H-1

    const float4* e4 = (const float4*)se;
    const float4* h4 = (const float4*)sh;

    float acc[4];
#pragma unroll
    for (int g = 0; g < 4; g++) {
        const int row = g * H + j;
        const float4* wi = (const float4*)(W_ih + (long long)row * H);
        const float4* wh = (const float4*)(W_hh + (long long)row * H);
        float s = 0.f;
#pragma unroll
        for (int t = lane; t < H / 4; t += 32) {
            float4 a = wi[t], b = e4[t];
            s += a.x * b.x + a.y * b.y + a.z * b.z + a.w * b.w;
            float4 c = wh[t], d = h4[t];
            s += c.x * d.x + c.y * d.y + c.z * d.z + c.w * d.w;
        }
        acc[g] = s;
    }
#pragma unroll
    for (int g = 0; g < 4; g++)
#pragma unroll
        for (int o = 16; o; o >>= 1)
            acc[g] += __shfl_xor_sync(0xFFFFFFFFu, acc[g], o);

    if (lane == 0) {
        const float gi = acc[0] + b_ih[j]         + b_hh[j];
        const float gf = acc[1] + b_ih[H + j]     + b_hh[H + j];
        const float gg = acc[2] + b_ih[2 * H + j] + b_hh[2 * H + j];
        const float go = acc[3] + b_ih[3 * H + j] + b_hh[3 * H + j];

        const float i_ = 1.f / (1.f + expf(-gi));
        const float f_ = 1.f / (1.f + expf(-gf));
        const float o_ = 1.f / (1.f + expf(-go));
        const float g_ = tanhf(gg);

        const float c_new = f_ * c0[j] + i_ * g_;
        const float h_new = o_ * tanhf(c_new);

        g_h[j] = h_new;
        out[V + j]     = h_new;
        out[V + H + j] = c_new;
    }
}

// ---------------------------------------------------------------------------
// K2: logits = out_W @ h_new + out_b. One warp per vocab row (4 KB of weights
// per row, float4 coalesced). h_new staged in shared memory per block.
// ---------------------------------------------------------------------------
__global__ void __launch_bounds__(256) k_logits(
    const float* __restrict__ out_W,
    const float* __restrict__ out_b)
{
    __shared__ float sh[H];
    for (int t = threadIdx.x; t < H; t += blockDim.x) sh[t] = g_h[t];
    __syncthreads();

    const int row  = (blockIdx.x * blockDim.x + threadIdx.x) >> 5;
    const int lane = threadIdx.x & 31;
    if (row >= V) return;

    const float4* w  = (const float4*)(out_W + (long long)row * H);
    const float4* h4 = (const float4*)sh;
    float s = 0.f;
#pragma unroll
    for (int t = lane; t < H / 4; t += 32) {
        float4 a = w[t], b = h4[t];
        s += a.x * b.x + a.y * b.y + a.z * b.z + a.w * b.w;
    }
#pragma unroll
    for (int o = 16; o; o >>= 1) s += __shfl_xor_sync(0xFFFFFFFFu, s, o);

    if (lane == 0) g_logits[row] = s + out_b[row];
}

// ---------------------------------------------------------------------------
// K3: logZ = max + log(sum(exp(logits - max))). Single block; 600 KB of
// logits traffic is tiny vs the 200 MB matvec.
// ---------------------------------------------------------------------------
__global__ void __launch_bounds__(1024) k_logsumexp()
{
    __shared__ float red[1024];
    const int tid = threadIdx.x;

    float m = -1e30f;
    for (int i = tid; i < V; i += 1024) m = fmaxf(m, g_logits[i]);
    red[tid] = m;
    __syncthreads();
    for (int s = 512; s; s >>= 1) {
        if (tid < s) red[tid] = fmaxf(red[tid], red[tid + s]);
        __syncthreads();
    }
    const float M = red[0];
    __syncthreads();

    float sum = 0.f;
    for (int i = tid; i < V; i += 1024) sum += expf(g_logits[i] - M);
    red[tid] = sum;
    __syncthreads();
    for (int s = 512; s; s >>= 1) {
        if (tid < s) red[tid] += red[tid + s];
        __syncthreads();
    }
    if (tid == 0) g_logZ = M + logf(red[0]);
}

// ---------------------------------------------------------------------------
// K4: log_probs = logits - logZ
// ---------------------------------------------------------------------------
__global__ void __launch_bounds__(256) k_sub(float* __restrict__ out)
{
    const int i = blockIdx.x * blockDim.x + threadIdx.x;
    if (i < V) out[i] = g_logits[i] - g_logZ;
}

extern "C" void kernel_launch(void* const* d_in, const int* in_sizes, int n_in,
                              void* d_out, int out_size)
{
    (void)in_sizes; (void)n_in; (void)out_size;
    const long long* tok  = (const long long*)d_in[0];
    const float* h0   = (const float*)d_in[1];
    const float* c0   = (const float*)d_in[2];
    // d_in[3] encoder_outputs, d_in[5..8] attn/comb params: dead code, skipped
    const float* emb  = (const float*)d_in[4];
    const float* W_ih = (const float*)d_in[9];
    const float* W_hh = (const float*)d_in[10];
    const float* b_ih = (const float*)d_in[11];
    const float* b_hh = (const float*)d_in[12];
    const float* outW = (const float*)d_in[13];
    const float* outb = (const float*)d_in[14];
    float* out = (float*)d_out;

    k_lstm<<<256, 128>>>(tok, emb, h0, c0, W_ih, W_hh, b_ih, b_hh, out);
    k_logits<<<(V * 32 + 255) / 256, 256>>>(outW, outb);
    k_logsumexp<<<1, 1024>>>();
    k_sub<<<(V + 255) / 256, 256>>>(out);
}

// round 2
// speedup vs baseline: 1.1398x; 1.1398x over previous
#include <cuda_runtime.h>

// AttnDecoder single decode step, fully fused persistent kernel.
// Live dataflow only (attention branch in the reference is dead code):
//   e = emb[tok]
//   gates = W_ih@e + b_ih + W_hh@h0 + b_hh ; LSTM cell -> h_new, c_new
//   logits = out_W @ h_new + out_b ; log_softmax
// Output layout (float32, out_size = V + 2H):
//   [0, V)  log_probs   [V, V+H) h_new   [V+H, V+2H) c_new

#define H 1024
#define V 50000
#define NBLK 148
#define NTHR 1024
#define NWARPS_BLK (NTHR / 32)          // 32
#define NWARP_TOT (NBLK * NWARPS_BLK)   // 4736

// Scratch (__device__ globals; no allocations allowed)
__device__ float g_gates[4 * H];
__device__ float g_pm[NBLK];
__device__ float g_ps[NBLK];
__device__ unsigned g_cnt[2];
__device__ unsigned g_gen[2];

// Sense-reversing grid barrier. All NBLK blocks are co-resident (1/SM).
__device__ __forceinline__ void gridbar(int id)
{
    __threadfence();          // publish this thread's prior writes
    __syncthreads();
    if (threadIdx.x == 0) {
        volatile unsigned* genp = &g_gen[id];
        const unsigned gen = *genp;              // read gen BEFORE arriving
        const unsigned t = atomicAdd(&g_cnt[id], 1u);
        if (t == NBLK - 1) {
            g_cnt[id] = 0;
            __threadfence();
            atomicAdd(&g_gen[id], 1u);           // release
        } else {
            while (*genp == gen) __nanosleep(64);
        }
    }
    __syncthreads();
    __threadfence();          // acquire side
}

// Streaming log-sum-exp merge of (m1,s1) <- (m1,s1)+(m2,s2)
__device__ __forceinline__ void lse_merge(float& m1, float& s1, float m2, float s2)
{
    const float M = fmaxf(m1, m2);
    s1 = s1 * expf(m1 - M) + s2 * expf(m2 - M);
    m1 = M;
}

__global__ void __launch_bounds__(NTHR, 1) k_fused(
    const long long* __restrict__ tok_p,
    const float* __restrict__ emb,
    const float* __restrict__ h0,
    const float* __restrict__ c0,
    const float* __restrict__ W_ih,
    const float* __restrict__ W_hh,
    const float* __restrict__ b_ih,
    const float* __restrict__ b_hh,
    const float* __restrict__ out_W,
    const float* __restrict__ out_b,
    float* __restrict__ out)
{
    __shared__ float se[H];       // embedded token
    __shared__ float sh[H];       // h0, later reused as h_new
    __shared__ float sm_m[NWARPS_BLK];
    __shared__ float sm_s[NWARPS_BLK];
    __shared__ float s_logZ;

    const int tid  = threadIdx.x;
    const int lane = tid & 31;
    const int wid  = tid >> 5;
    const int gwarp = blockIdx.x * NWARPS_BLK + wid;

    // ---- Phase 0: stage e and h0 in this block's smem --------------------
    {
        const long long tok = *tok_p;
        const float* erow = emb + tok * (long long)H;
        for (int t = tid; t < H; t += NTHR) {
            se[t] = erow[t];
            sh[t] = h0[t];
        }
    }
    __syncthreads();

    // ---- Phase 1: gate rows. One warp per row of the 4H x H matvec pair --
    if (gwarp < 4 * H) {
        const int row = gwarp;
        const float4* wi = (const float4*)(W_ih + (long long)row * H);
        const float4* wh = (const float4*)(W_hh + (long long)row * H);
        const float4* e4 = (const float4*)se;
        const float4* h4 = (const float4*)sh;
        float s = 0.f;
#pragma unroll
        for (int k = 0; k < H / 128; k++) {
            const int t = lane + k * 32;
            float4 a = wi[t], b = e4[t];
            s += a.x * b.x + a.y * b.y + a.z * b.z + a.w * b.w;
            float4 c = wh[t], d = h4[t];
            s += c.x * d.x + c.y * d.y + c.z * d.z + c.w * d.w;
        }
#pragma unroll
        for (int o = 16; o; o >>= 1) s += __shfl_xor_sync(0xFFFFFFFFu, s, o);
        if (lane == 0) g_gates[row] = s + b_ih[row] + b_hh[row];
    }

    gridbar(0);   // all gate pre-activations visible

    // ---- Phase 1b: LSTM elementwise; every block builds h_new in its smem
    for (int j = tid; j < H; j += NTHR) {
        const float gi = g_gates[j];
        const float gf = g_gates[H + j];
        const float gg = g_gates[2 * H + j];
        const float go = g_gates[3 * H + j];
        const float i_ = 1.f / (1.f + expf(-gi));
        const float f_ = 1.f / (1.f + expf(-gf));
        const float o_ = 1.f / (1.f + expf(-go));
        const float g_ = tanhf(gg);
        const float c_new = f_ * c0[j] + i_ * g_;
        const float h_new = o_ * tanhf(c_new);
        sh[j] = h_new;                       // reuse sh as h_new
        if (blockIdx.x == 0) {
            out[V + j]     = h_new;
            out[V + H + j] = c_new;
        }
    }
    __syncthreads();

    // ---- Phase 2: logits matvec + streaming per-warp logsumexp ----------
    float m_w = -1e30f, s_w = 0.f;
    {
        const float4* h4 = (const float4*)sh;
        for (int row = gwarp; row < V; row += NWARP_TOT) {
            const float4* w = (const float4*)(out_W + (long long)row * H);
            float s = 0.f;
#pragma unroll
            for (int k = 0; k < H / 128; k++) {
                const int t = lane + k * 32;
                float4 a = w[t], b = h4[t];
                s += a.x * b.x + a.y * b.y + a.z * b.z + a.w * b.w;
            }
#pragma unroll
            for (int o = 16; o; o >>= 1) s += __shfl_xor_sync(0xFFFFFFFFu, s, o);
            const float x = s + out_b[row];      // uniform load, broadcast
            if (lane == 0) out[row] = x;
            // streaming lse (identical in all lanes)
            if (x > m_w) { s_w = s_w * expf(m_w - x) + 1.f; m_w = x; }
            else         { s_w += expf(x - m_w); }
        }
    }
    if (lane == 0) { sm_m[wid] = m_w; sm_s[wid] = s_w; }
    __syncthreads();
    if (wid == 0) {
        float m = sm_m[lane], s = sm_s[lane];
#pragma unroll
        for (int o = 16; o; o >>= 1) {
            const float m2 = __shfl_xor_sync(0xFFFFFFFFu, m, o);
            const float s2 = __shfl_xor_sync(0xFFFFFFFFu, s, o);
            lse_merge(m, s, m2, s2);
        }
        if (lane == 0) { g_pm[blockIdx.x] = m; g_ps[blockIdx.x] = s; }
    }

    gridbar(1);   // all logits + partials visible

    // ---- Phase 3: combine 148 partials (warp 0, fixed order), subtract --
    if (wid == 0) {
        float m = -1e30f, s = 0.f;
        for (int b = lane; b < NBLK; b += 32)
            lse_merge(m, s, g_pm[b], g_ps[b]);
#pragma unroll
        for (int o = 16; o; o >>= 1) {
            const float m2 = __shfl_xor_sync(0xFFFFFFFFu, m, o);
            const float s2 = __shfl_xor_sync(0xFFFFFFFFu, s, o);
            lse_merge(m, s, m2, s2);
        }
        if (lane == 0) s_logZ = m + logf(s);
    }
    __syncthreads();
    const float logZ = s_logZ;
    for (int i = blockIdx.x * NTHR + tid; i < V; i += NBLK * NTHR)
        out[i] -= logZ;
}

extern "C" void kernel_launch(void* const* d_in, const int* in_sizes, int n_in,
                              void* d_out, int out_size)
{
    (void)in_sizes; (void)n_in; (void)out_size;
    const long long* tok  = (const long long*)d_in[0];
    const float* h0   = (const float*)d_in[1];
    const float* c0   = (const float*)d_in[2];
    // d_in[3] encoder_outputs, d_in[5..8] attn/comb params: dead code, skipped
    const float* emb  = (const float*)d_in[4];
    const float* W_ih = (const float*)d_in[9];
    const float* W_hh = (const float*)d_in[10];
    const float* b_ih = (const float*)d_in[11];
    const float* b_hh = (const float*)d_in[12];
    const float* outW = (const float*)d_in[13];
    const float* outb = (const float*)d_in[14];
    float* out = (float*)d_out;

    k_fused<<<NBLK, NTHR>>>(tok, emb, h0, c0, W_ih, W_hh, b_ih, b_hh,
                            outW, outb, out);
}